// round 9
// baseline (speedup 1.0000x reference)
#include <cuda_runtime.h>

#define R_RUNS 128
#define T_STEPS 1024
#define N_AGENTS 128
#define PF 3
#define NPHASE 1087
#define WPB 8          // warps per block -> 2 warps per SMSP
#define NBLK (R_RUNS / WPB)

typedef unsigned long long u64;

__device__ __forceinline__ float ex2_approx(float x) {
    float r;
    asm("ex2.approx.f32 %0, %1;" : "=f"(r) : "f"(x));
    return r;
}
__device__ __forceinline__ float rcp_approx(float x) {
    float r;
    asm("rcp.approx.f32 %0, %1;" : "=f"(r) : "f"(x));
    return r;
}
__device__ __forceinline__ u64 pk(float lo, float hi) {
    u64 r;
    asm("mov.b64 %0, {%1, %2};" : "=l"(r) : "f"(lo), "f"(hi));
    return r;
}
__device__ __forceinline__ void upk(float& lo, float& hi, u64 v) {
    asm("mov.b64 {%0, %1}, %2;" : "=f"(lo), "=f"(hi) : "l"(v));
}
__device__ __forceinline__ u64 fma2(u64 a, u64 b, u64 c) {
    u64 d;
    asm("fma.rn.f32x2 %0, %1, %2, %3;" : "=l"(d) : "l"(a), "l"(b), "l"(c));
    return d;
}

// MLP, sigmoid form: weights prescaled so layer-1 emits yS = S*(W1@inp + b1),
// S = -2*log2(e); s_j = 1/(1 + 2^{yS_j}); out = (2*W2)@s + (b2 - W2@1).
// Paired reciprocal: 1 rcp serves 2 hidden units.
#define MLP_BODY(Q, A_, B_, O0, O1, O2) do {                                   \
    u64 aa_ = pk((A_), (A_)), bb_ = pk((B_), (B_));                            \
    float y_[10], e_[10], d_[10];                                              \
    _Pragma("unroll")                                                          \
    for (int j2 = 0; j2 < 5; ++j2) {                                           \
        u64 y2_ = fma2(U3p[j2], bb_, fma2(U2p[j2], aa_, Q[j2]));               \
        upk(y_[2*j2], y_[2*j2+1], y2_);                                        \
    }                                                                          \
    _Pragma("unroll")                                                          \
    for (int j = 0; j < 10; ++j) e_[j] = ex2_approx(y_[j]);                    \
    _Pragma("unroll")                                                          \
    for (int j = 0; j < 10; ++j) d_[j] = e_[j] + 1.0f;                         \
    u64 s2_[5];                                                                \
    _Pragma("unroll")                                                          \
    for (int j2 = 0; j2 < 5; ++j2) {                                           \
        float m_ = d_[2*j2] * d_[2*j2+1];                                      \
        float r_ = rcp_approx(m_);                                             \
        s2_[j2] = pk(d_[2*j2+1] * r_, d_[2*j2] * r_);                          \
    }                                                                          \
    u64 a0_ = fma2(V0p[0], s2_[0], C20p);                                      \
    u64 a1_ = fma2(V1p[0], s2_[0], C21p);                                      \
    u64 a2_ = fma2(V2p[0], s2_[0], C22p);                                      \
    _Pragma("unroll")                                                          \
    for (int j2 = 1; j2 < 5; ++j2) {                                           \
        a0_ = fma2(V0p[j2], s2_[j2], a0_);                                     \
        a1_ = fma2(V1p[j2], s2_[j2], a1_);                                     \
        a2_ = fma2(V2p[j2], s2_[j2], a2_);                                     \
    }                                                                          \
    float l0_, h0_, l1_, h1_, l2_, h2_;                                        \
    upk(l0_, h0_, a0_); upk(l1_, h1_, a1_); upk(l2_, h2_, a2_);                \
    (O0) = l0_ + h0_; (O1) = l1_ + h1_; (O2) = l2_ + h2_;                      \
} while (0)

#define MAKE_Q(Q, X0, X1) do {                                                 \
    u64 xx0_ = pk((X0), (X0)), xx1_ = pk((X1), (X1));                          \
    _Pragma("unroll")                                                          \
    for (int j2 = 0; j2 < 5; ++j2)                                             \
        Q[j2] = fma2(U1p[j2], xx1_, fma2(U0p[j2], xx0_, C1p[j2]));             \
} while (0)

__global__ __launch_bounds__(32 * WPB, 1)
void com2net_sig2w(const float* __restrict__ runs,
                   const float* __restrict__ W1,
                   const float* __restrict__ b1,
                   const float* __restrict__ W2,
                   const float* __restrict__ b2,
                   float* __restrict__ out)
{
    const int k = threadIdx.x & 31;                       // lane: owns pairs 2k, 2k+1
    const int r = blockIdx.x * WPB + (threadIdx.x >> 5);  // one run per warp; 2 warps/SMSP

    // ---- prescale + pack weights over hidden-unit pairs ----
    const float S = -2.8853900817779268f;   // -2*log2(e)
    u64 U0p[5], U1p[5], U2p[5], U3p[5], C1p[5];
#pragma unroll
    for (int j2 = 0; j2 < 5; ++j2) {
        int j = 2 * j2;
        U0p[j2] = pk(W1[j*4+0] * S, W1[(j+1)*4+0] * S);
        U1p[j2] = pk(W1[j*4+1] * S, W1[(j+1)*4+1] * S);
        U2p[j2] = pk(W1[j*4+2] * S, W1[(j+1)*4+2] * S);
        U3p[j2] = pk(W1[j*4+3] * S, W1[(j+1)*4+3] * S);
        C1p[j2] = pk(b1[j] * S,     b1[j+1] * S);
    }
    u64 V0p[5], V1p[5], V2p[5], C20p, C21p, C22p;
    {
        float s0 = 0.f, s1 = 0.f, s2 = 0.f;
#pragma unroll
        for (int j = 0; j < 10; ++j) {
            s0 += W2[0*10 + j]; s1 += W2[1*10 + j]; s2 += W2[2*10 + j];
        }
#pragma unroll
        for (int j2 = 0; j2 < 5; ++j2) {
            int j = 2 * j2;
            V0p[j2] = pk(2.f * W2[0*10+j], 2.f * W2[0*10+j+1]);
            V1p[j2] = pk(2.f * W2[1*10+j], 2.f * W2[1*10+j+1]);
            V2p[j2] = pk(2.f * W2[2*10+j], 2.f * W2[2*10+j+1]);
        }
        C20p = pk(b2[0] - s0, 0.f);
        C21p = pk(b2[1] - s1, 0.f);
        C22p = pk(b2[2] - s2, 0.f);
    }

    // lane k owns pairs 2k (agents 4k,4k+1 @ t0 = p-2k) and 2k+1 (agents 4k+2,4k+3 @ t0-1)
    const float* xb0 = runs + (size_t)r * T_STEPS * N_AGENTS * 2 + (size_t)k * 8;
    const float* xb1 = xb0 + 4;
    float*       ob  = out  + (size_t)r * T_STEPS * N_AGENTS;

    // prefetch queues: xq0[d] = x(t0 = p-2k+d), xq1[d] = x(t1 = t0-1+d)
    float4 xq0[PF], xq1[PF];
#pragma unroll
    for (int d = 0; d < PF; ++d) {
        int t0c = d - 2 * k;       t0c = max(0, min(T_STEPS - 1, t0c));
        int t1c = d - 2 * k - 1;   t1c = max(0, min(T_STEPS - 1, t1c));
        xq0[d] = *(const float4*)(xb0 + (size_t)t0c * (N_AGENTS * 2));
        xq1[d] = *(const float4*)(xb1 + (size_t)t1c * (N_AGENTS * 2));
    }

    // loop-carried: o1/o2 of both B MLPs from previous phase
    float o1B0 = 0.f, o2B0 = 0.f, o1B1 = 0.f, o2B1 = 0.f;

#pragma unroll 1
    for (int p = 0; p < NPHASE; ++p) {
        const int t0 = p - 2 * k;
        const int t1 = t0 - 1;
        const bool act0 = ((unsigned)t0 < (unsigned)T_STEPS);
        const bool act1 = ((unsigned)t1 < (unsigned)T_STEPS);

        // a-input for A0: lane k-1's B1.o2 from prev phase (same t0)
        const float aUp = __shfl_up_sync(0xffffffffu, o2B1, 1);

        // prefetch t + PF
        int t0c = t0 + PF;  t0c = max(0, min(T_STEPS - 1, t0c));
        int t1c = t1 + PF;  t1c = max(0, min(T_STEPS - 1, t1c));
        const float4 n0 = *(const float4*)(xb0 + (size_t)t0c * (N_AGENTS * 2));
        const float4 n1 = *(const float4*)(xb1 + (size_t)t1c * (N_AGENTS * 2));
        const float4 h0 = xq0[0], h1 = xq1[0];
#pragma unroll
        for (int d = 0; d < PF - 1; ++d) { xq0[d] = xq0[d + 1]; xq1[d] = xq1[d + 1]; }
        xq0[PF - 1] = n0; xq1[PF - 1] = n1;

        // x-partials for all 4 MLPs
        u64 q0a[5], q0b[5], q1a[5], q1b[5];
        MAKE_Q(q0a, h0.x, h0.y);
        MAKE_Q(q0b, h0.z, h0.w);
        MAKE_Q(q1a, h1.x, h1.y);
        MAKE_Q(q1b, h1.z, h1.w);

        // ---- A-stage: two independent MLPs ----
        const float aA0 = (k == 0) ? 0.f : aUp;       // comm[0] never written
        const float bA0 = (t0 >= 1) ? o1B0 : 0.f;
        const float aA1 = o2B0;                        // own B0.o2 prev phase (t1)
        const float bA1 = (t1 >= 1) ? o1B1 : 0.f;

        float o0A0, o1A0, o2A0, o0A1, o1A1, o2A1;
        MLP_BODY(q0a, aA0, bA0, o0A0, o1A0, o2A0);
        MLP_BODY(q1a, aA1, bA1, o0A1, o1A1, o2A1);

        // b-input for B1: lane k+1's A0.o1 (this phase, its t0 = our t1-1)
        const float bDn = __shfl_down_sync(0xffffffffu, o1A0, 1);

        // ---- B-stage: two independent MLPs ----
        const float bB0 = (t0 >= 1) ? o1A1 : 0.f;     // own A1.o1 (t0-1)
        const float bB1 = (t1 >= 1) ? ((k == 31) ? 0.f : bDn) : 0.f;  // comm[257] never written

        float o0B0, n_o1B0, n_o2B0, o0B1, n_o1B1, n_o2B1;
        MLP_BODY(q0b, o2A0, bB0, o0B0, n_o1B0, n_o2B0);
        MLP_BODY(q1b, o2A1, bB1, o0B1, n_o1B1, n_o2B1);

        o1B0 = n_o1B0; o2B0 = n_o2B0;
        o1B1 = n_o1B1; o2B1 = n_o2B1;

        if (act0) *(float2*)(ob + (size_t)t0 * N_AGENTS + 4 * k)     = make_float2(o0A0, o0B0);
        if (act1) *(float2*)(ob + (size_t)t1 * N_AGENTS + 4 * k + 2) = make_float2(o0A1, o0B1);
    }
}

extern "C" void kernel_launch(void* const* d_in, const int* in_sizes, int n_in,
                              void* d_out, int out_size)
{
    const float* runs = (const float*)d_in[0];
    const float* W1   = (const float*)d_in[1];
    const float* b1   = (const float*)d_in[2];
    const float* W2   = (const float*)d_in[3];
    const float* b2   = (const float*)d_in[4];
    float* out = (float*)d_out;
    com2net_sig2w<<<NBLK, 32 * WPB>>>(runs, W1, b1, W2, b2, out);
}

// round 10
// speedup vs baseline: 1.4720x; 1.4720x over previous
#include <cuda_runtime.h>

#define R_RUNS 128
#define T_STEPS 1024
#define N_AGENTS 128
#define PF 3
#define NPHASE 1087

typedef unsigned long long u64;

__device__ __forceinline__ float tanh_approx(float x) {
    float r;
    asm("tanh.approx.f32 %0, %1;" : "=f"(r) : "f"(x));
    return r;
}
__device__ __forceinline__ u64 pk(float lo, float hi) {
    u64 r;
    asm("mov.b64 %0, {%1, %2};" : "=l"(r) : "f"(lo), "f"(hi));
    return r;
}
__device__ __forceinline__ void upk(float& lo, float& hi, u64 v) {
    asm("mov.b64 {%0, %1}, %2;" : "=f"(lo), "=f"(hi) : "l"(v));
}
__device__ __forceinline__ u64 fma2(u64 a, u64 b, u64 c) {
    u64 d;
    asm("fma.rn.f32x2 %0, %1, %2, %3;" : "=l"(d) : "l"(a), "l"(b), "l"(c));
    return d;
}

// layer-1 y vector: Y[10] = W1@[x-part(Q), a, b] (Q holds x partials + b1)
#define L1Y(Y, Q, A_, B_) do {                                                 \
    u64 aa_ = pk((A_), (A_)), bb_ = pk((B_), (B_));                            \
    _Pragma("unroll")                                                          \
    for (int j2 = 0; j2 < 5; ++j2) {                                           \
        u64 y2_ = fma2(U3p[j2], bb_, fma2(U2p[j2], aa_, (Q)[j2]));             \
        upk((Y)[2*j2], (Y)[2*j2+1], y2_);                                      \
    }                                                                          \
} while (0)

// layer-2 from hidden vector H[10]
#define L2(H, O0, O1, O2) do {                                                 \
    u64 s_[5];                                                                 \
    _Pragma("unroll")                                                          \
    for (int j2 = 0; j2 < 5; ++j2) s_[j2] = pk((H)[2*j2], (H)[2*j2+1]);        \
    u64 a0_ = fma2(V0p[0], s_[0], C20p);                                       \
    u64 a1_ = fma2(V1p[0], s_[0], C21p);                                       \
    u64 a2_ = fma2(V2p[0], s_[0], C22p);                                       \
    _Pragma("unroll")                                                          \
    for (int j2 = 1; j2 < 5; ++j2) {                                           \
        a0_ = fma2(V0p[j2], s_[j2], a0_);                                      \
        a1_ = fma2(V1p[j2], s_[j2], a1_);                                      \
        a2_ = fma2(V2p[j2], s_[j2], a2_);                                      \
    }                                                                          \
    float l0_, h0_, l1_, h1_, l2_, h2_;                                        \
    upk(l0_, h0_, a0_); upk(l1_, h1_, a1_); upk(l2_, h2_, a2_);                \
    (O0) = l0_ + h0_; (O1) = l1_ + h1_; (O2) = l2_ + h2_;                      \
} while (0)

#define MAKE_Q(Q, X0, X1) do {                                                 \
    u64 xx0_ = pk((X0), (X0)), xx1_ = pk((X1), (X1));                          \
    _Pragma("unroll")                                                          \
    for (int j2 = 0; j2 < 5; ++j2)                                             \
        (Q)[j2] = fma2(U1p[j2], xx1_, fma2(U0p[j2], xx0_, C1p[j2]));           \
} while (0)

__global__ __launch_bounds__(32, 1)
void com2net_fused(const float* __restrict__ runs,
                   const float* __restrict__ W1,
                   const float* __restrict__ b1,
                   const float* __restrict__ W2,
                   const float* __restrict__ b2,
                   float* __restrict__ out)
{
    const int k = threadIdx.x;   // lane owns pairs 2k (agents 4k,4k+1 @ t0) and 2k+1 (agents 4k+2,4k+3 @ t0-1)
    const int r = blockIdx.x;

    // ---- pack weights over hidden-unit pairs ----
    u64 U0p[5], U1p[5], U2p[5], U3p[5], C1p[5];
#pragma unroll
    for (int j2 = 0; j2 < 5; ++j2) {
        int j = 2 * j2;
        U0p[j2] = pk(W1[j*4+0], W1[(j+1)*4+0]);
        U1p[j2] = pk(W1[j*4+1], W1[(j+1)*4+1]);
        U2p[j2] = pk(W1[j*4+2], W1[(j+1)*4+2]);
        U3p[j2] = pk(W1[j*4+3], W1[(j+1)*4+3]);
        C1p[j2] = pk(b1[j],     b1[j+1]);
    }
    u64 V0p[5], V1p[5], V2p[5], C20p, C21p, C22p;
#pragma unroll
    for (int j2 = 0; j2 < 5; ++j2) {
        int j = 2 * j2;
        V0p[j2] = pk(W2[0*10+j], W2[0*10+j+1]);
        V1p[j2] = pk(W2[1*10+j], W2[1*10+j+1]);
        V2p[j2] = pk(W2[2*10+j], W2[2*10+j+1]);
    }
    C20p = pk(b2[0], 0.f);
    C21p = pk(b2[1], 0.f);
    C22p = pk(b2[2], 0.f);

    const float* xb0 = runs + (size_t)r * T_STEPS * N_AGENTS * 2 + (size_t)k * 8;
    const float* xb1 = xb0 + 4;
    float*       ob  = out  + (size_t)r * T_STEPS * N_AGENTS;

    // prefetch queues: xq0[d] = x(t0 = p-2k+d), xq1[d] = x(t1 = t0-1+d)
    float4 xq0[PF], xq1[PF];
#pragma unroll
    for (int d = 0; d < PF; ++d) {
        int t0c = d - 2 * k;       t0c = max(0, min(T_STEPS - 1, t0c));
        int t1c = d - 2 * k - 1;   t1c = max(0, min(T_STEPS - 1, t1c));
        xq0[d] = *(const float4*)(xb0 + (size_t)t0c * (N_AGENTS * 2));
        xq1[d] = *(const float4*)(xb1 + (size_t)t1c * (N_AGENTS * 2));
    }

    // loop-carried: o1/o2 of both B MLPs from previous phase
    float o1B0 = 0.f, o2B0 = 0.f, o1B1 = 0.f, o2B1 = 0.f;

#pragma unroll 1
    for (int p = 0; p < NPHASE; ++p) {
        const int t0 = p - 2 * k;
        const int t1 = t0 - 1;
        const bool act0 = ((unsigned)t0 < (unsigned)T_STEPS);
        const bool act1 = ((unsigned)t1 < (unsigned)T_STEPS);

        // a-input for A0: lane k-1's B1.o2 from prev phase (same t0)
        const float aUp = __shfl_up_sync(0xffffffffu, o2B1, 1);
        const float aA0 = (k == 0) ? 0.f : aUp;       // comm[0] never written
        const float bA0 = (t0 >= 1) ? o1B0 : 0.f;
        const float aA1 = o2B0;                        // own B0.o2 prev phase (t1)
        const float bA1 = (t1 >= 1) ? o1B1 : 0.f;

        const float4 h0 = xq0[0], h1 = xq1[0];

        // ---- A-stage layer 1: both MLPs' y vectors (20 independent chains) ----
        u64 qa0[5], qa1[5];
        MAKE_Q(qa0, h0.x, h0.y);
        MAKE_Q(qa1, h1.x, h1.y);
        float yA0[10], yA1[10];
        L1Y(yA0, qa0, aA0, bA0);
        L1Y(yA1, qa1, aA1, bA1);

        // ---- 20 independent tanh, issued back-to-back ----
        float hA0[10], hA1[10];
#pragma unroll
        for (int j = 0; j < 10; ++j) {
            hA0[j] = tanh_approx(yA0[j]);
            hA1[j] = tanh_approx(yA1[j]);
        }

        // ---- filler in A-tanh latency shadow: B q-partials + global prefetch ----
        u64 qb0[5], qb1[5];
        MAKE_Q(qb0, h0.z, h0.w);
        MAKE_Q(qb1, h1.z, h1.w);
        int t0c = t0 + PF;  t0c = max(0, min(T_STEPS - 1, t0c));
        int t1c = t1 + PF;  t1c = max(0, min(T_STEPS - 1, t1c));
        const float4 n0 = *(const float4*)(xb0 + (size_t)t0c * (N_AGENTS * 2));
        const float4 n1 = *(const float4*)(xb1 + (size_t)t1c * (N_AGENTS * 2));

        // ---- A-stage layer 2 (both MLPs) ----
        float o0A0, o1A0, o2A0, o0A1, o1A1, o2A1;
        L2(hA0, o0A0, o1A0, o2A0);
        L2(hA1, o0A1, o1A1, o2A1);

        // b-input for B1: lane k+1's A0.o1 (this phase, its t0 = our t1-1)
        const float bDn = __shfl_down_sync(0xffffffffu, o1A0, 1);
        const float bB0 = (t0 >= 1) ? o1A1 : 0.f;     // own A1.o1 (t0-1)
        const float bB1 = (t1 >= 1) ? ((k == 31) ? 0.f : bDn) : 0.f;  // comm[257] never written

        // ---- B-stage layer 1 ----
        float yB0[10], yB1[10];
        L1Y(yB0, qb0, o2A0, bB0);
        L1Y(yB1, qb1, o2A1, bB1);

        // ---- 20 independent tanh ----
        float hB0[10], hB1[10];
#pragma unroll
        for (int j = 0; j < 10; ++j) {
            hB0[j] = tanh_approx(yB0[j]);
            hB1[j] = tanh_approx(yB1[j]);
        }

        // ---- filler in B-tanh shadow: rotate prefetch queues ----
#pragma unroll
        for (int d = 0; d < PF - 1; ++d) { xq0[d] = xq0[d + 1]; xq1[d] = xq1[d + 1]; }
        xq0[PF - 1] = n0; xq1[PF - 1] = n1;

        // ---- B-stage layer 2 ----
        float o0B0, n_o1B0, n_o2B0, o0B1, n_o1B1, n_o2B1;
        L2(hB0, o0B0, n_o1B0, n_o2B0);
        L2(hB1, o0B1, n_o1B1, n_o2B1);

        o1B0 = n_o1B0; o2B0 = n_o2B0;
        o1B1 = n_o1B1; o2B1 = n_o2B1;

        if (act0) *(float2*)(ob + (size_t)t0 * N_AGENTS + 4 * k)     = make_float2(o0A0, o0B0);
        if (act1) *(float2*)(ob + (size_t)t1 * N_AGENTS + 4 * k + 2) = make_float2(o0A1, o0B1);
    }
}

extern "C" void kernel_launch(void* const* d_in, const int* in_sizes, int n_in,
                              void* d_out, int out_size)
{
    const float* runs = (const float*)d_in[0];
    const float* W1   = (const float*)d_in[1];
    const float* b1   = (const float*)d_in[2];
    const float* W2   = (const float*)d_in[3];
    const float* b2   = (const float*)d_in[4];
    float* out = (float*)d_out;
    com2net_fused<<<R_RUNS, 32>>>(runs, W1, b1, W2, b2, out);
}

// round 11
// speedup vs baseline: 2.3754x; 1.6138x over previous
#include <cuda_runtime.h>

#define T_STEPS 1024
#define N_AGENTS 128
#define R_RUNS 128
#define PF 3
#define NPHASE 1089   // 3*363 >= 1087; extra phases fully store-gated

typedef unsigned long long u64;

__device__ __forceinline__ float tanh_approx(float x) {
    float r;
    asm("tanh.approx.f32 %0, %1;" : "=f"(r) : "f"(x));
    return r;
}
__device__ __forceinline__ u64 pk(float lo, float hi) {
    u64 r;
    asm("mov.b64 %0, {%1, %2};" : "=l"(r) : "f"(lo), "f"(hi));
    return r;
}
__device__ __forceinline__ void upk(float& lo, float& hi, u64 v) {
    asm("mov.b64 {%0, %1}, %2;" : "=f"(lo), "=f"(hi) : "l"(v));
}
__device__ __forceinline__ u64 fma2(u64 a, u64 b, u64 c) {
    u64 d;
    asm("fma.rn.f32x2 %0, %1, %2, %3;" : "=l"(d) : "l"(a), "l"(b), "l"(c));
    return d;
}
// predicated vector store: no BSSY/BSYNC
__device__ __forceinline__ void st2_pred(float* p, unsigned t, float v0, float v1) {
    asm volatile("{\n\t.reg .pred q;\n\tsetp.lt.u32 q, %0, 1024;\n\t@q st.global.v2.f32 [%1], {%2, %3};\n\t}"
                 :: "r"(t), "l"(p), "f"(v0), "f"(v1) : "memory");
}
__device__ __forceinline__ void st2_pred_off(float* p, unsigned t, float v0, float v1) {
    asm volatile("{\n\t.reg .pred q;\n\tsetp.lt.u32 q, %0, 1024;\n\t@q st.global.v2.f32 [%1+-504], {%2, %3};\n\t}"
                 :: "r"(t), "l"(p), "f"(v0), "f"(v1) : "memory");
}

#define L1Y(Y, Q, A_, B_) do {                                                 \
    u64 aa_ = pk((A_), (A_)), bb_ = pk((B_), (B_));                            \
    _Pragma("unroll")                                                          \
    for (int j2 = 0; j2 < 5; ++j2) {                                           \
        u64 y2_ = fma2(U3p[j2], bb_, fma2(U2p[j2], aa_, (Q)[j2]));             \
        upk((Y)[2*j2], (Y)[2*j2+1], y2_);                                      \
    }                                                                          \
} while (0)

#define L2(H, O0, O1, O2) do {                                                 \
    u64 s_[5];                                                                 \
    _Pragma("unroll")                                                          \
    for (int j2 = 0; j2 < 5; ++j2) s_[j2] = pk((H)[2*j2], (H)[2*j2+1]);        \
    u64 a0_ = fma2(V0p[0], s_[0], C20p);                                       \
    u64 a1_ = fma2(V1p[0], s_[0], C21p);                                       \
    u64 a2_ = fma2(V2p[0], s_[0], C22p);                                       \
    _Pragma("unroll")                                                          \
    for (int j2 = 1; j2 < 5; ++j2) {                                           \
        a0_ = fma2(V0p[j2], s_[j2], a0_);                                      \
        a1_ = fma2(V1p[j2], s_[j2], a1_);                                      \
        a2_ = fma2(V2p[j2], s_[j2], a2_);                                      \
    }                                                                          \
    float l0_, h0_, l1_, h1_, l2_, h2_;                                        \
    upk(l0_, h0_, a0_); upk(l1_, h1_, a1_); upk(l2_, h2_, a2_);                \
    (O0) = l0_ + h0_; (O1) = l1_ + h1_; (O2) = l2_ + h2_;                      \
} while (0)

#define MAKE_Q(Q, X0, X1) do {                                                 \
    u64 xx0_ = pk((X0), (X0)), xx1_ = pk((X1), (X1));                          \
    _Pragma("unroll")                                                          \
    for (int j2 = 0; j2 < 5; ++j2)                                             \
        (Q)[j2] = fma2(U1p[j2], xx1_, fma2(U0p[j2], xx0_, C1p[j2]));           \
} while (0)

// One phase with static queue slot I (0..2).
#define PHASE_ITER(I) do {                                                     \
    const float aUp = __shfl_up_sync(0xffffffffu, o2B1, 1);                    \
    const float aA0 = (k == 0) ? 0.f : aUp;                                    \
    const float bA0 = (t0 >= 1) ? o1B0 : 0.f;                                  \
    const float aA1 = o2B0;                                                    \
    const float bA1 = (t0 >= 2) ? o1B1 : 0.f;                                  \
    const float4 h0 = xq0[I], h1 = xq1[I];                                     \
    /* refill slot I with t+PF (running pointers, conditional advance) */      \
    const float4 n0 = *(const float4*)pf0;                                     \
    const float4 n1 = *(const float4*)pf1;                                     \
    xq0[I] = n0; xq1[I] = n1;                                                  \
    pf0 = ((unsigned)(t0 + PF) <= (T_STEPS - 2)) ? (pf0 + N_AGENTS * 2) : pf0; \
    pf1 = ((unsigned)(t0 - 1 + PF) <= (T_STEPS - 2)) ? (pf1 + N_AGENTS * 2) : pf1; \
    /* A-stage */                                                              \
    u64 qa0[5], qa1[5];                                                        \
    MAKE_Q(qa0, h0.x, h0.y);                                                   \
    MAKE_Q(qa1, h1.x, h1.y);                                                   \
    float yA0[10], yA1[10];                                                    \
    L1Y(yA0, qa0, aA0, bA0);                                                   \
    L1Y(yA1, qa1, aA1, bA1);                                                   \
    float hA0[10], hA1[10];                                                    \
    _Pragma("unroll")                                                          \
    for (int j = 0; j < 10; ++j) {                                             \
        hA0[j] = tanh_approx(yA0[j]);                                          \
        hA1[j] = tanh_approx(yA1[j]);                                          \
    }                                                                          \
    u64 qb0[5], qb1[5];                                                        \
    MAKE_Q(qb0, h0.z, h0.w);                                                   \
    MAKE_Q(qb1, h1.z, h1.w);                                                   \
    float o0A0, o1A0, o2A0, o0A1, o1A1, o2A1;                                  \
    L2(hA0, o0A0, o1A0, o2A0);                                                 \
    L2(hA1, o0A1, o1A1, o2A1);                                                 \
    const float bDn = __shfl_down_sync(0xffffffffu, o1A0, 1);                  \
    const float bB0 = (t0 >= 1) ? o1A1 : 0.f;                                  \
    const float bB1 = (t0 >= 2) ? ((k == 31) ? 0.f : bDn) : 0.f;               \
    /* B-stage */                                                              \
    float yB0[10], yB1[10];                                                    \
    L1Y(yB0, qb0, o2A0, bB0);                                                  \
    L1Y(yB1, qb1, o2A1, bB1);                                                  \
    float hB0[10], hB1[10];                                                    \
    _Pragma("unroll")                                                          \
    for (int j = 0; j < 10; ++j) {                                             \
        hB0[j] = tanh_approx(yB0[j]);                                          \
        hB1[j] = tanh_approx(yB1[j]);                                          \
    }                                                                          \
    float o0B0, n_o1B0, n_o2B0, o0B1, n_o1B1, n_o2B1;                          \
    L2(hB0, o0B0, n_o1B0, n_o2B0);                                             \
    L2(hB1, o0B1, n_o1B1, n_o2B1);                                             \
    o1B0 = n_o1B0; o2B0 = n_o2B0;                                              \
    o1B1 = n_o1B1; o2B1 = n_o2B1;                                              \
    /* predicated stores: pair0 at t0 (offset 0), pair1 at t0-1 (-504B) */     \
    st2_pred(optr, (unsigned)t0, o0A0, o0B0);                                  \
    st2_pred_off(optr, (unsigned)(t0 - 1), o0A1, o0B1);                        \
    optr += N_AGENTS;                                                          \
    ++t0;                                                                      \
} while (0)

__global__ __launch_bounds__(32, 1)
void com2net_np(const float* __restrict__ runs,
                const float* __restrict__ W1,
                const float* __restrict__ b1,
                const float* __restrict__ W2,
                const float* __restrict__ b2,
                float* __restrict__ out)
{
    const int k = threadIdx.x;   // lane owns pairs 2k (agents 4k,4k+1 @ t0) and 2k+1 (agents 4k+2,4k+3 @ t0-1)
    const int r = blockIdx.x;

    // ---- pack weights over hidden-unit pairs ----
    u64 U0p[5], U1p[5], U2p[5], U3p[5], C1p[5];
#pragma unroll
    for (int j2 = 0; j2 < 5; ++j2) {
        int j = 2 * j2;
        U0p[j2] = pk(W1[j*4+0], W1[(j+1)*4+0]);
        U1p[j2] = pk(W1[j*4+1], W1[(j+1)*4+1]);
        U2p[j2] = pk(W1[j*4+2], W1[(j+1)*4+2]);
        U3p[j2] = pk(W1[j*4+3], W1[(j+1)*4+3]);
        C1p[j2] = pk(b1[j],     b1[j+1]);
    }
    u64 V0p[5], V1p[5], V2p[5], C20p, C21p, C22p;
#pragma unroll
    for (int j2 = 0; j2 < 5; ++j2) {
        int j = 2 * j2;
        V0p[j2] = pk(W2[0*10+j], W2[0*10+j+1]);
        V1p[j2] = pk(W2[1*10+j], W2[1*10+j+1]);
        V2p[j2] = pk(W2[2*10+j], W2[2*10+j+1]);
    }
    C20p = pk(b2[0], 0.f);
    C21p = pk(b2[1], 0.f);
    C22p = pk(b2[2], 0.f);

    const float* xb0 = runs + (size_t)r * T_STEPS * N_AGENTS * 2 + (size_t)k * 8;
    const float* xb1 = xb0 + 4;

    // prefetch queues + running prefetch pointers (point at t = clamp(t0+PF))
    float4 xq0[PF], xq1[PF];
#pragma unroll
    for (int d = 0; d < PF; ++d) {
        int t0c = d - 2 * k;       t0c = max(0, min(T_STEPS - 1, t0c));
        int t1c = d - 2 * k - 1;   t1c = max(0, min(T_STEPS - 1, t1c));
        xq0[d] = *(const float4*)(xb0 + (size_t)t0c * (N_AGENTS * 2));
        xq1[d] = *(const float4*)(xb1 + (size_t)t1c * (N_AGENTS * 2));
    }
    const float* pf0;
    const float* pf1;
    {
        int t0c = PF - 2 * k;       t0c = max(0, min(T_STEPS - 1, t0c));
        int t1c = PF - 2 * k - 1;   t1c = max(0, min(T_STEPS - 1, t1c));
        pf0 = xb0 + (size_t)t0c * (N_AGENTS * 2);
        pf1 = xb1 + (size_t)t1c * (N_AGENTS * 2);
    }

    // running output pointer: &out[r][t0][4k]; valid only when 0<=t0<T (store predicated)
    float* optr = out + (size_t)r * T_STEPS * N_AGENTS + (size_t)4 * k
                      + (long long)(-2 * k) * N_AGENTS;
    int t0 = -2 * k;

    float o1B0 = 0.f, o2B0 = 0.f, o1B1 = 0.f, o2B1 = 0.f;

#pragma unroll 1
    for (int pb = 0; pb < NPHASE; pb += 3) {
        PHASE_ITER(0);
        PHASE_ITER(1);
        PHASE_ITER(2);
    }
}

extern "C" void kernel_launch(void* const* d_in, const int* in_sizes, int n_in,
                              void* d_out, int out_size)
{
    const float* runs = (const float*)d_in[0];
    const float* W1   = (const float*)d_in[1];
    const float* b1   = (const float*)d_in[2];
    const float* W2   = (const float*)d_in[3];
    const float* b2   = (const float*)d_in[4];
    float* out = (float*)d_out;
    com2net_np<<<R_RUNS, 32>>>(runs, W1, b1, W2, b2, out);
}